// round 3
// baseline (speedup 1.0000x reference)
#include <cuda_runtime.h>
#include <cstdint>

#define BS_ROWS     1024                      // B*S
#define VOCAB       50257
#define DMODEL      768
#define D4          (DMODEL / 4)              // 192 float4 per row
#define TOTAL_ELEMS (BS_ROWS * (long long)VOCAB)   // 51,463,168
#define TOTAL_F4    (TOTAL_ELEMS / 4)              // 12,865,792

// ---------------------------------------------------------------------------
// Slow path: the finding thread writes out[row,:] = v * weight[col,:] alone.
// 192 float4 loads+stores, unrolled for MLP. Fires ~1024 times total.
// ---------------------------------------------------------------------------
__device__ __noinline__ void emit_row(long long g, float v,
                                      const float4* __restrict__ w4,
                                      float4* __restrict__ out4)
{
    int row = (int)(g / VOCAB);
    int col = (int)(g - (long long)row * VOCAB);
    const float4* __restrict__ wr = w4 + (long long)col * D4;
    float4* __restrict__ orow     = out4 + (long long)row * D4;
    #pragma unroll 8
    for (int j = 0; j < D4; j++) {
        float4 t = __ldg(&wr[j]);
        t.x *= v; t.y *= v; t.z *= v; t.w *= v;
        orow[j] = t;
    }
}

__device__ __forceinline__ void check_vec(uint4 a, long long i,
                                          const float4* __restrict__ w4,
                                          float4* __restrict__ out4)
{
    // integer OR-tree -> single predicate per 16B in the hot path
    if (a.x | a.y | a.z | a.w) {
        long long base = i * 4;
        if (__uint_as_float(a.x) != 0.0f) emit_row(base + 0, __uint_as_float(a.x), w4, out4);
        if (__uint_as_float(a.y) != 0.0f) emit_row(base + 1, __uint_as_float(a.y), w4, out4);
        if (__uint_as_float(a.z) != 0.0f) emit_row(base + 2, __uint_as_float(a.z), w4, out4);
        if (__uint_as_float(a.w) != 0.0f) emit_row(base + 3, __uint_as_float(a.w), w4, out4);
    }
}

// ---------------------------------------------------------------------------
// Fused kernel: R1-style streaming scan (no warp sync anywhere) + inline emit.
// ---------------------------------------------------------------------------
__global__ void __launch_bounds__(256, 8)
fused_embed_kernel(const uint4* __restrict__ oh4,
                   const float4* __restrict__ w4,
                   float4* __restrict__ out4)
{
    const long long stride = (long long)gridDim.x * blockDim.x;
    long long i = (long long)blockIdx.x * blockDim.x + threadIdx.x;

    // 4-way unrolled grid-stride loop; loads are independent -> high MLP.
    for (; i + 3 * stride < TOTAL_F4; i += 4 * stride) {
        uint4 a = __ldcs(&oh4[i]);
        uint4 b = __ldcs(&oh4[i + stride]);
        uint4 c = __ldcs(&oh4[i + 2 * stride]);
        uint4 d = __ldcs(&oh4[i + 3 * stride]);

        check_vec(a, i,              w4, out4);
        check_vec(b, i + stride,     w4, out4);
        check_vec(c, i + 2 * stride, w4, out4);
        check_vec(d, i + 3 * stride, w4, out4);
    }
    // tail
    for (; i < TOTAL_F4; i += stride) {
        uint4 a = __ldcs(&oh4[i]);
        check_vec(a, i, w4, out4);
    }
}

// ---------------------------------------------------------------------------
extern "C" void kernel_launch(void* const* d_in, const int* in_sizes, int n_in,
                              void* d_out, int out_size)
{
    const float* one_hot = nullptr;
    const float* weight  = nullptr;
    for (int i = 0; i < n_in; i++) {
        if (in_sizes[i] == (int)TOTAL_ELEMS)     one_hot = (const float*)d_in[i];
        else if (in_sizes[i] == VOCAB * DMODEL)  weight  = (const float*)d_in[i];
    }

    // Same scan config that measured 5.2 TB/s in R1.
    const int threads = 256;
    const int blocks  = 148 * 16;   // 2368
    fused_embed_kernel<<<blocks, threads>>>((const uint4*)one_hot,
                                            (const float4*)weight,
                                            (float4*)d_out);
}

// round 4
// speedup vs baseline: 1.8702x; 1.8702x over previous
#include <cuda_runtime.h>
#include <cstdint>

#define BS_ROWS     1024                      // B*S
#define VOCAB       50257
#define DMODEL      768
#define D4          (DMODEL / 4)              // 192 float4 per row
#define TOTAL_ELEMS (BS_ROWS * (long long)VOCAB)   // 51,463,168
#define TOTAL_F4    (TOTAL_ELEMS / 4)              // 12,865,792

// ---------------------------------------------------------------------------
// Fused kernel, deferred block-level emission:
//   phase 1: R1-identical streaming scan; rare path records (g, val) to smem
//   phase 2: __syncthreads; block cooperatively emits each recorded row
// ---------------------------------------------------------------------------
__global__ void __launch_bounds__(256)
fused_embed_kernel(const uint4* __restrict__ oh4,
                   const float4* __restrict__ w4,
                   float4* __restrict__ out4)
{
    __shared__ int       s_cnt;
    __shared__ long long s_g[BS_ROWS];     // global element index of nonzero
    __shared__ float     s_v[BS_ROWS];     // its value

    if (threadIdx.x == 0) s_cnt = 0;
    __syncthreads();

    const long long stride = (long long)gridDim.x * blockDim.x;
    long long i = (long long)blockIdx.x * blockDim.x + threadIdx.x;

    // ---- phase 1: scan (hot loop identical in shape to R1) ----
    for (; i + 3 * stride < TOTAL_F4; i += 4 * stride) {
        uint4 a = __ldg(&oh4[i]);
        uint4 b = __ldg(&oh4[i + stride]);
        uint4 c = __ldg(&oh4[i + 2 * stride]);
        uint4 d = __ldg(&oh4[i + 3 * stride]);

        #pragma unroll
        for (int u = 0; u < 4; u++) {
            uint4 v = (u == 0) ? a : (u == 1) ? b : (u == 2) ? c : d;
            if (v.x | v.y | v.z | v.w) {                     // rare
                long long base = (i + (long long)u * stride) * 4;
                float f[4] = { __uint_as_float(v.x), __uint_as_float(v.y),
                               __uint_as_float(v.z), __uint_as_float(v.w) };
                #pragma unroll
                for (int k = 0; k < 4; k++) {
                    if (f[k] != 0.0f) {
                        int slot = atomicAdd(&s_cnt, 1);
                        s_g[slot] = base + k;
                        s_v[slot] = f[k];
                    }
                }
            }
        }
    }
    // tail
    for (; i < TOTAL_F4; i += stride) {
        uint4 v = __ldg(&oh4[i]);
        if (v.x | v.y | v.z | v.w) {
            long long base = i * 4;
            float f[4] = { __uint_as_float(v.x), __uint_as_float(v.y),
                           __uint_as_float(v.z), __uint_as_float(v.w) };
            #pragma unroll
            for (int k = 0; k < 4; k++) {
                if (f[k] != 0.0f) {
                    int slot = atomicAdd(&s_cnt, 1);
                    s_g[slot] = base + k;
                    s_v[slot] = f[k];
                }
            }
        }
    }

    // ---- phase 2: block-cooperative emission ----
    __syncthreads();
    const int cnt = s_cnt;
    const int t   = threadIdx.x;
    for (int e = 0; e < cnt; e++) {
        long long g = s_g[e];
        float     v = s_v[e];
        int row = (int)(g / VOCAB);
        int col = (int)(g - (long long)row * VOCAB);
        if (t < D4) {                                 // 192 of 256 threads
            float4 w = __ldg(&w4[(long long)col * D4 + t]);
            w.x *= v; w.y *= v; w.z *= v; w.w *= v;
            out4[(long long)row * D4 + t] = w;
        }
    }
}

// ---------------------------------------------------------------------------
extern "C" void kernel_launch(void* const* d_in, const int* in_sizes, int n_in,
                              void* d_out, int out_size)
{
    const float* one_hot = nullptr;
    const float* weight  = nullptr;
    for (int i = 0; i < n_in; i++) {
        if (in_sizes[i] == (int)TOTAL_ELEMS)     one_hot = (const float*)d_in[i];
        else if (in_sizes[i] == VOCAB * DMODEL)  weight  = (const float*)d_in[i];
    }

    // R1 scan config (measured 5.2 TB/s).
    const int threads = 256;
    const int blocks  = 148 * 16;   // 2368
    fused_embed_kernel<<<blocks, threads>>>((const uint4*)one_hot,
                                            (const float4*)weight,
                                            (float4*)d_out);
}

// round 5
// speedup vs baseline: 1.9743x; 1.0557x over previous
#include <cuda_runtime.h>
#include <cstdint>

#define BS_ROWS     1024                      // B*S
#define VOCAB       50257
#define DMODEL      768
#define D4          (DMODEL / 4)              // 192 float4 per row
#define TOTAL_ELEMS (BS_ROWS * (long long)VOCAB)   // 51,463,168
#define TOTAL_F4    12865792u                 // TOTAL_ELEMS/4 = 256 * 50257
#define NBLOCKS     1733                      // 50257 = 29 * 1733
#define NTHREADS    256
// stride = NBLOCKS*NTHREADS = 443,648 ; 29 * stride == TOTAL_F4 exactly

// ---------------------------------------------------------------------------
// Record one nonzero into the block's shared buffer (rare: 1024 total events).
// ---------------------------------------------------------------------------
__device__ __forceinline__ void record4(uint4 v, unsigned i,
                                        int* s_cnt, int* s_g, float* s_v)
{
    if (v.x | v.y | v.z | v.w) {                       // almost never taken
        unsigned base = i * 4u;
        float f[4] = { __uint_as_float(v.x), __uint_as_float(v.y),
                       __uint_as_float(v.z), __uint_as_float(v.w) };
        #pragma unroll
        for (int k = 0; k < 4; k++) {
            if (f[k] != 0.0f) {
                int slot = atomicAdd(s_cnt, 1);
                s_g[slot] = (int)(base + k);           // < 2^26, fits int
                s_v[slot] = f[k];
            }
        }
    }
}

// ---------------------------------------------------------------------------
// Fused kernel: exact-fit scan (29 f4/thread, zero bounds checks) + deferred
// block-level emission.
// ---------------------------------------------------------------------------
__global__ void __launch_bounds__(NTHREADS)
fused_embed_kernel(const uint4* __restrict__ oh4,
                   const float4* __restrict__ w4,
                   float4* __restrict__ out4)
{
    __shared__ int   s_cnt;
    __shared__ int   s_g[BS_ROWS];
    __shared__ float s_v[BS_ROWS];

    if (threadIdx.x == 0) s_cnt = 0;
    __syncthreads();

    const unsigned stride = NBLOCKS * NTHREADS;        // 443,648
    unsigned i = blockIdx.x * NTHREADS + threadIdx.x;

    // ---- phase 1: scan. 29 = 3*8 + 4 + 1, fully bounds-check free ----
    #pragma unroll 1
    for (int r = 0; r < 3; r++) {
        uint4 v[8];
        #pragma unroll
        for (int u = 0; u < 8; u++) v[u] = __ldg(&oh4[i + u * stride]);
        #pragma unroll
        for (int u = 0; u < 8; u++)
            record4(v[u], i + u * stride, &s_cnt, s_g, s_v);
        i += 8u * stride;
    }
    {
        uint4 v[4];
        #pragma unroll
        for (int u = 0; u < 4; u++) v[u] = __ldg(&oh4[i + u * stride]);
        #pragma unroll
        for (int u = 0; u < 4; u++)
            record4(v[u], i + u * stride, &s_cnt, s_g, s_v);
        i += 4u * stride;
    }
    {
        uint4 v = __ldg(&oh4[i]);
        record4(v, i, &s_cnt, s_g, s_v);
    }

    // ---- phase 2: block-cooperative emission ----
    __syncthreads();
    const int cnt = s_cnt;
    const int t   = threadIdx.x;
    for (int e = 0; e < cnt; e++) {
        unsigned g = (unsigned)s_g[e];
        float    v = s_v[e];
        int row = (int)(g / VOCAB);
        int col = (int)(g - (unsigned)row * VOCAB);
        if (t < D4) {                                  // 192 of 256 threads
            float4 w = __ldg(&w4[col * D4 + t]);
            w.x *= v; w.y *= v; w.z *= v; w.w *= v;
            out4[row * D4 + t] = w;
        }
    }
}

// ---------------------------------------------------------------------------
extern "C" void kernel_launch(void* const* d_in, const int* in_sizes, int n_in,
                              void* d_out, int out_size)
{
    const float* one_hot = nullptr;
    const float* weight  = nullptr;
    for (int i = 0; i < n_in; i++) {
        if (in_sizes[i] == (int)TOTAL_ELEMS)     one_hot = (const float*)d_in[i];
        else if (in_sizes[i] == VOCAB * DMODEL)  weight  = (const float*)d_in[i];
    }

    fused_embed_kernel<<<NBLOCKS, NTHREADS>>>((const uint4*)one_hot,
                                              (const float4*)weight,
                                              (float4*)d_out);
}